// round 16
// baseline (speedup 1.0000x reference)
#include <cuda_runtime.h>

#define BB     32
#define NATOM  256
#define NN     100
#define NF     42
#define NH1    50
#define NH2    50
#define APW    4                      // atoms per warp (mlp weight-LDS amortization)
#define ROWLEN (NN * NF * 3)          // 12600 floats per (b,n)
#define NGRP   (NN * NF / 4)          // 1050 groups of 12 floats (= 3 float4 = 4 entries)
#define SGRP   256                    // groups per cp.async stage (1 group/thread)
#define NSTG   5                      // ceil(1050/256); last stage has 26 groups
#define BUFF4  (SGRP * 3)             // float4 per full stage buffer (768 = 12288 B)

// dE (grad of sum Ei wrt image), [B, NATOM, NF]. Device global => no allocation.
__device__ float g_dE[BB * NATOM * NF];
// 1 if neighbor buffer is int32, 0 if int64. Written by mlp_kernel block 0.
__device__ int   g_nbr_is32;

__device__ __forceinline__ float tanh_fast(float x) {
    float y;
    asm("tanh.approx.f32 %0, %1;" : "=f"(y) : "f"(x));
    return y;
}

__device__ __forceinline__ void cp16(void* dst_smem, const void* src_gmem) {
    const unsigned d = (unsigned)__cvta_generic_to_shared(dst_smem);
    asm volatile("cp.async.cg.shared.global [%0], [%1], 16;" :: "r"(d), "l"(src_gmem));
}

// ---------------------------------------------------------------------------
// Kernel 1: MLP fwd + input-grad bwd, 4 atoms per warp (R14 WIN — unchanged).
// LDS-crossbar-bound: each weight LDS feeds 4 atoms (8 FFMAs).
// Block 0 also detects neighbor dtype (int64 values in [0,256] => all odd
// 32-bit words zero; int32 essentially never).
// ---------------------------------------------------------------------------
__global__ void __launch_bounds__(256) mlp_kernel(
    const float* __restrict__ image,
    const unsigned int* __restrict__ nbr_words,
    const float* __restrict__ W0a, const float* __restrict__ b0a,
    const float* __restrict__ W1a, const float* __restrict__ b1a,
    const float* __restrict__ W2a, const float* __restrict__ b2a,
    const float* __restrict__ W0b, const float* __restrict__ b0b,
    const float* __restrict__ W1b, const float* __restrict__ b1b,
    const float* __restrict__ W2b, const float* __restrict__ b2b,
    float* __restrict__ Ei, float* __restrict__ Etot)
{
    __shared__ float sW0[NF * NH1];
    __shared__ float sW1[NH1 * NH2];
    __shared__ float sW2[NH2];
    __shared__ float sb0[NH1];
    __shared__ float sb1[NH2];
    __shared__ float sxw[8][APW * NF];
    __shared__ float sh0s[8][APW * NH1];
    __shared__ float sh1s[8][APW * NH2];
    __shared__ int s_any;

    const int tid  = threadIdx.x;
    const int warp = tid >> 5;
    const int lane = tid & 31;
    const int abase = blockIdx.x * 32 + warp * APW;
    const int type  = ((abase % NATOM) >= 128) ? 1 : 0;

    const float* W0 = type ? W0b : W0a;
    const float* b0 = type ? b0b : b0a;
    const float* W1 = type ? W1b : W1a;
    const float* b1 = type ? b1b : b1a;
    const float* W2 = type ? W2b : W2a;
    const float  b2v = type ? b2b[0] : b2a[0];

    int any = 0;
    if (blockIdx.x == 0) {
        if (tid == 0) s_any = 0;
        for (int i = tid; i < 4096; i += 256)
            if (nbr_words[2 * i + 1] != 0u) any = 1;
    }

    for (int i = tid; i < NF * NH1; i += 256)  sW0[i] = W0[i];
    for (int i = tid; i < NH1 * NH2; i += 256) sW1[i] = W1[i];
    if (tid < NH2) sW2[tid] = W2[tid];
    if (tid < NH1) sb0[tid] = b0[tid];
    if (tid < NH2) sb1[tid] = b1[tid];
    __syncthreads();

    if (blockIdx.x == 0) {
        if (any) atomicOr(&s_any, 1);
        __syncthreads();
        if (tid == 0) g_nbr_is32 = s_any;
    }

    float* sx  = sxw[warp];
    float* sh0 = sh0s[warp];
    float* sh1 = sh1s[warp];

    const int j1 = lane;
    const int j2 = lane + 32;
    const bool has2h = (j2 < NH1);

    for (int i = lane; i < APW * NF; i += 32)
        sx[i] = image[(size_t)abase * NF + i];
    __syncwarp();

    {
        float s1[APW], s2[APW];
        #pragma unroll
        for (int t = 0; t < APW; t++) { s1[t] = sb0[j1]; s2[t] = has2h ? sb0[j2] : 0.0f; }
        #pragma unroll
        for (int f = 0; f < NF; f++) {
            const float w1 = sW0[f * NH1 + j1];
            const float w2 = has2h ? sW0[f * NH1 + j2] : 0.0f;
            #pragma unroll
            for (int t = 0; t < APW; t++) {
                const float xv = sx[t * NF + f];
                s1[t] += xv * w1;
                s2[t] += xv * w2;
            }
        }
        #pragma unroll
        for (int t = 0; t < APW; t++) {
            sh0[t * NH1 + j1] = tanh_fast(s1[t]);
            if (has2h) sh0[t * NH1 + j2] = tanh_fast(s2[t]);
        }
    }
    __syncwarp();

    {
        float s1[APW], s2[APW];
        #pragma unroll
        for (int t = 0; t < APW; t++) { s1[t] = sb1[j1]; s2[t] = has2h ? sb1[j2] : 0.0f; }
        #pragma unroll
        for (int i = 0; i < NH1; i++) {
            const float w1 = sW1[i * NH2 + j1];
            const float w2 = has2h ? sW1[i * NH2 + j2] : 0.0f;
            #pragma unroll
            for (int t = 0; t < APW; t++) {
                const float hv = sh0[t * NH1 + i];
                s1[t] += hv * w1;
                s2[t] += hv * w2;
            }
        }
        #pragma unroll
        for (int t = 0; t < APW; t++) {
            sh1[t * NH2 + j1] = tanh_fast(s1[t]);
            if (has2h) sh1[t * NH2 + j2] = tanh_fast(s2[t]);
        }
    }
    __syncwarp();

    {
        const float w2a = sW2[j1];
        const float w2b = has2h ? sW2[j2] : 0.0f;
        #pragma unroll
        for (int t = 0; t < APW; t++) {
            float v = sh1[t * NH2 + j1] * w2a;
            if (has2h) v += sh1[t * NH2 + j2] * w2b;
            #pragma unroll
            for (int o = 16; o > 0; o >>= 1) v += __shfl_down_sync(0xffffffffu, v, o);
            if (lane == 0) {
                const float e = v + b2v;
                Ei[abase + t] = e;
                atomicAdd(&Etot[(abase + t) >> 8], e);
            }
        }
    }
    __syncwarp();

    {
        const float w2a = sW2[j1];
        const float w2b = has2h ? sW2[j2] : 0.0f;
        #pragma unroll
        for (int t = 0; t < APW; t++) {
            const float h1v = sh1[t * NH2 + j1];
            sh1[t * NH2 + j1] = w2a * (1.0f - h1v * h1v);
            if (has2h) {
                const float h2v = sh1[t * NH2 + j2];
                sh1[t * NH2 + j2] = w2b * (1.0f - h2v * h2v);
            }
        }
    }
    __syncwarp();

    {
        float s1[APW], s2[APW];
        #pragma unroll
        for (int t = 0; t < APW; t++) { s1[t] = 0.0f; s2[t] = 0.0f; }
        #pragma unroll
        for (int j = 0; j < NH2; j++) {
            const float w1 = sW1[j1 * NH2 + j];
            const float w2 = has2h ? sW1[j2 * NH2 + j] : 0.0f;
            #pragma unroll
            for (int t = 0; t < APW; t++) {
                const float gv = sh1[t * NH2 + j];
                s1[t] += w1 * gv;
                s2[t] += w2 * gv;
            }
        }
        #pragma unroll
        for (int t = 0; t < APW; t++) {
            const float h1v = sh0[t * NH1 + j1];
            sh0[t * NH1 + j1] = s1[t] * (1.0f - h1v * h1v);
            if (has2h) {
                const float h2v = sh0[t * NH1 + j2];
                sh0[t * NH1 + j2] = s2[t] * (1.0f - h2v * h2v);
            }
        }
    }
    __syncwarp();

    {
        const int f2 = lane + 32;
        const bool has2f = (f2 < NF);
        float s1[APW], s2[APW];
        #pragma unroll
        for (int t = 0; t < APW; t++) { s1[t] = 0.0f; s2[t] = 0.0f; }
        #pragma unroll
        for (int i = 0; i < NH1; i++) {
            const float w1 = sW0[lane * NH1 + i];
            const float w2 = has2f ? sW0[f2 * NH1 + i] : 0.0f;
            #pragma unroll
            for (int t = 0; t < APW; t++) {
                const float gv = sh0[t * NH1 + i];
                s1[t] += w1 * gv;
                s2[t] += w2 * gv;
            }
        }
        #pragma unroll
        for (int t = 0; t < APW; t++) {
            g_dE[(size_t)(abase + t) * NF + lane] = s1[t];
            if (has2f) g_dE[(size_t)(abase + t) * NF + f2] = s2[t];
        }
    }
}

// ---------------------------------------------------------------------------
// Kernel 3: Force — cp.async double-buffered stream.
// Registers stay ~35 (prefetch lives in smem, not regs — sidesteps the
// 30-reg/8-CTA cliff that killed R9/R12). Stages 0,1 issued BEFORE the dE
// gather so DRAM is busy through the prologue. 1 group/thread/stage:
// 1 LDS.128 (w) + 3 LDS.128 (v, conflict-free 48B stride) + 12 FFMAs.
// ---------------------------------------------------------------------------
__global__ void __launch_bounds__(256, 5) force_kernel(
    const float* __restrict__ dfeat,
    const void* __restrict__ neighbor,
    float* __restrict__ force)
{
    __shared__ __align__(16) float4 sbuf[2][BUFF4];  // 24576 B
    __shared__ __align__(16) float  sdE[NN * NF];    // 16800 B
    __shared__ int   snbr[NN];
    __shared__ float sred[3][8];

    const int tid = threadIdx.x;
    const int bn  = blockIdx.x;          // b*NATOM + n
    const int b   = bn >> 8;

    // neighbor indices first (LDG in flight during stage issue)
    if (tid < NN) {
        int j;
        if (g_nbr_is32) j = ((const int*)neighbor)[(size_t)bn * NN + tid];
        else            j = (int)((const long long*)neighbor)[(size_t)bn * NN + tid];
        snbr[tid] = j;
    }

    // issue stages 0 and 1 immediately — DRAM busy from block start
    const float4* __restrict__ df4 =
        (const float4*)(dfeat + (size_t)bn * ROWLEN);
    #pragma unroll
    for (int s = 0; s < 2; s++) {
        const float4* src = df4 + 3 * s * SGRP;
        #pragma unroll
        for (int i = 0; i < 3; i++)                  // 768 f4 = 3 per thread
            cp16(&sbuf[s][tid + 256 * i], &src[tid + 256 * i]);
        asm volatile("cp.async.commit_group;");
    }

    __syncthreads();                     // snbr visible

    // gather dE rows (L2 hits) while cp.async stages stream from DRAM
    {
        const float* dEb = g_dE + (size_t)b * NATOM * NF;
        float2* sdE2 = (float2*)sdE;
        for (int i2 = tid; i2 < NN * NF / 2; i2 += 256) {
            const int k  = (2 * i2) / NF;
            const int f  = 2 * i2 - k * NF;
            const int j  = snbr[k];
            float2 v;
            if (j == 0) { v.x = 0.0f; v.y = 0.0f; }
            else        { v = *(const float2*)(dEb + (j - 1) * NF + f); }
            sdE2[i2] = v;
        }
    }
    __syncthreads();

    const float4* __restrict__ sdE4 = (const float4*)sdE;
    float a0 = 0.0f, a1 = 0.0f, a2 = 0.0f;

    for (int st = 0; st < NSTG; st++) {
        asm volatile("cp.async.wait_group 1;" ::: "memory");
        __syncthreads();                 // stage st data visible to all

        const int g = st * SGRP + tid;
        if (g < NGRP) {
            const float4 w  = sdE4[g];
            const float4* bp = &sbuf[st & 1][3 * tid];
            const float4 v0 = bp[0], v1 = bp[1], v2 = bp[2];
            a0 += w.x * v0.x;  a1 += w.x * v0.y;  a2 += w.x * v0.z;
            a0 += w.y * v0.w;  a1 += w.y * v1.x;  a2 += w.y * v1.y;
            a0 += w.z * v1.z;  a1 += w.z * v1.w;  a2 += w.z * v2.x;
            a0 += w.w * v2.y;  a1 += w.w * v2.z;  a2 += w.w * v2.w;
        }
        __syncthreads();                 // all reads done before buffer reuse

        const int sn = st + 2;
        if (sn < NSTG) {
            const int nf4 = (sn < NSTG - 1) ? BUFF4 : 3 * (NGRP - (NSTG - 1) * SGRP);
            const float4* src = df4 + 3 * sn * SGRP;
            float4* dst = sbuf[sn & 1];
            for (int i = tid; i < nf4; i += 256) cp16(&dst[i], &src[i]);
        }
        asm volatile("cp.async.commit_group;");   // uniform count (empty ok)
    }

    #pragma unroll
    for (int o = 16; o > 0; o >>= 1) {
        a0 += __shfl_down_sync(0xffffffffu, a0, o);
        a1 += __shfl_down_sync(0xffffffffu, a1, o);
        a2 += __shfl_down_sync(0xffffffffu, a2, o);
    }
    const int warp = tid >> 5;
    if ((tid & 31) == 0) { sred[0][warp] = a0; sred[1][warp] = a1; sred[2][warp] = a2; }
    __syncthreads();

    if (tid < 3) {
        float s = 0.0f;
        #pragma unroll
        for (int w = 0; w < 8; w++) s += sred[tid][w];
        force[(size_t)bn * 3 + tid] = s;
    }
}

// ---------------------------------------------------------------------------
extern "C" void kernel_launch(void* const* d_in, const int* in_sizes, int n_in,
                              void* d_out, int out_size)
{
    const float* image    = (const float*)d_in[0];
    const float* dfeat    = (const float*)d_in[1];
    const void*  neighbor = d_in[2];
    const float* W0_0 = (const float*)d_in[3];
    const float* b0_0 = (const float*)d_in[4];
    const float* W1_0 = (const float*)d_in[5];
    const float* b1_0 = (const float*)d_in[6];
    const float* W2_0 = (const float*)d_in[7];
    const float* b2_0 = (const float*)d_in[8];
    const float* W0_1 = (const float*)d_in[9];
    const float* b0_1 = (const float*)d_in[10];
    const float* W1_1 = (const float*)d_in[11];
    const float* b1_1 = (const float*)d_in[12];
    const float* W2_1 = (const float*)d_in[13];
    const float* b2_1 = (const float*)d_in[14];

    float* out   = (float*)d_out;
    float* Etot  = out;                       // [32]
    float* Ei    = out + BB;                  // [32*256]
    float* Force = out + BB + BB * NATOM;     // [32*256*3]

    cudaMemsetAsync(Etot, 0, BB * sizeof(float));

    mlp_kernel<<<BB * NATOM / 32, 256>>>(
        image, (const unsigned int*)neighbor,
        W0_0, b0_0, W1_0, b1_0, W2_0, b2_0,
        W0_1, b0_1, W1_1, b1_1, W2_1, b2_1,
        Ei, Etot);
    force_kernel<<<BB * NATOM, 256>>>(dfeat, neighbor, Force);
}

// round 17
// speedup vs baseline: 1.1294x; 1.1294x over previous
#include <cuda_runtime.h>

#define BB     32
#define NATOM  256
#define NN     100
#define NF     42
#define NH1    50
#define NH2    50
#define APW    4                      // atoms per warp (mlp weight-LDS amortization)
#define ROWLEN (NN * NF * 3)          // 12600 floats per (b,n)
#define NGRP   (NN * NF / 4)          // 1050 groups of 12 floats (= 3 float4 = 4 entries)
#define HALF_ATOMS (BB * NATOM / 2)   // 4096
#define HALF_BN    (BB * NATOM / 2)   // 4096 (b,n) rows per half

// dE (grad of sum Ei wrt image), [B, NATOM, NF]. Device global => no allocation.
__device__ float g_dE[BB * NATOM * NF];
// 1 if neighbor buffer is int32, 0 if int64. Written by mlp block 0 of half A.
__device__ int   g_nbr_is32;

__device__ __forceinline__ float tanh_fast(float x) {
    float y;
    asm("tanh.approx.f32 %0, %1;" : "=f"(y) : "f"(x));
    return y;
}

// ---------------------------------------------------------------------------
// Kernel 1: MLP fwd + input-grad bwd, 4 atoms per warp (R14 WIN, + atom0 offset).
// LDS-crossbar-bound: each weight LDS feeds 4 atoms (8 FFMAs).
// Half-A block 0 also detects neighbor dtype (int64 values in [0,256] => all
// odd 32-bit words zero; int32 essentially never).
// ---------------------------------------------------------------------------
__global__ void __launch_bounds__(256) mlp_kernel(
    int atom0,
    const float* __restrict__ image,
    const unsigned int* __restrict__ nbr_words,
    const float* __restrict__ W0a, const float* __restrict__ b0a,
    const float* __restrict__ W1a, const float* __restrict__ b1a,
    const float* __restrict__ W2a, const float* __restrict__ b2a,
    const float* __restrict__ W0b, const float* __restrict__ b0b,
    const float* __restrict__ W1b, const float* __restrict__ b1b,
    const float* __restrict__ W2b, const float* __restrict__ b2b,
    float* __restrict__ Ei, float* __restrict__ Etot)
{
    __shared__ float sW0[NF * NH1];
    __shared__ float sW1[NH1 * NH2];
    __shared__ float sW2[NH2];
    __shared__ float sb0[NH1];
    __shared__ float sb1[NH2];
    __shared__ float sxw[8][APW * NF];
    __shared__ float sh0s[8][APW * NH1];
    __shared__ float sh1s[8][APW * NH2];
    __shared__ int s_any;

    const int tid  = threadIdx.x;
    const int warp = tid >> 5;
    const int lane = tid & 31;
    const int abase = atom0 + blockIdx.x * 32 + warp * APW;
    const int type  = ((abase % NATOM) >= 128) ? 1 : 0;

    const float* W0 = type ? W0b : W0a;
    const float* b0 = type ? b0b : b0a;
    const float* W1 = type ? W1b : W1a;
    const float* b1 = type ? b1b : b1a;
    const float* W2 = type ? W2b : W2a;
    const float  b2v = type ? b2b[0] : b2a[0];

    // neighbor-dtype detection (half A, block 0 only)
    int any = 0;
    const bool detect = (atom0 == 0) && (blockIdx.x == 0);
    if (detect) {
        if (tid == 0) s_any = 0;
        for (int i = tid; i < 4096; i += 256)
            if (nbr_words[2 * i + 1] != 0u) any = 1;
    }

    for (int i = tid; i < NF * NH1; i += 256)  sW0[i] = W0[i];
    for (int i = tid; i < NH1 * NH2; i += 256) sW1[i] = W1[i];
    if (tid < NH2) sW2[tid] = W2[tid];
    if (tid < NH1) sb0[tid] = b0[tid];
    if (tid < NH2) sb1[tid] = b1[tid];
    __syncthreads();

    if (detect) {
        if (any) atomicOr(&s_any, 1);
        __syncthreads();
        if (tid == 0) g_nbr_is32 = s_any;
    }

    float* sx  = sxw[warp];
    float* sh0 = sh0s[warp];
    float* sh1 = sh1s[warp];

    const int j1 = lane;
    const int j2 = lane + 32;
    const bool has2h = (j2 < NH1);

    for (int i = lane; i < APW * NF; i += 32)
        sx[i] = image[(size_t)abase * NF + i];
    __syncwarp();

    {
        float s1[APW], s2[APW];
        #pragma unroll
        for (int t = 0; t < APW; t++) { s1[t] = sb0[j1]; s2[t] = has2h ? sb0[j2] : 0.0f; }
        #pragma unroll
        for (int f = 0; f < NF; f++) {
            const float w1 = sW0[f * NH1 + j1];
            const float w2 = has2h ? sW0[f * NH1 + j2] : 0.0f;
            #pragma unroll
            for (int t = 0; t < APW; t++) {
                const float xv = sx[t * NF + f];
                s1[t] += xv * w1;
                s2[t] += xv * w2;
            }
        }
        #pragma unroll
        for (int t = 0; t < APW; t++) {
            sh0[t * NH1 + j1] = tanh_fast(s1[t]);
            if (has2h) sh0[t * NH1 + j2] = tanh_fast(s2[t]);
        }
    }
    __syncwarp();

    {
        float s1[APW], s2[APW];
        #pragma unroll
        for (int t = 0; t < APW; t++) { s1[t] = sb1[j1]; s2[t] = has2h ? sb1[j2] : 0.0f; }
        #pragma unroll
        for (int i = 0; i < NH1; i++) {
            const float w1 = sW1[i * NH2 + j1];
            const float w2 = has2h ? sW1[i * NH2 + j2] : 0.0f;
            #pragma unroll
            for (int t = 0; t < APW; t++) {
                const float hv = sh0[t * NH1 + i];
                s1[t] += hv * w1;
                s2[t] += hv * w2;
            }
        }
        #pragma unroll
        for (int t = 0; t < APW; t++) {
            sh1[t * NH2 + j1] = tanh_fast(s1[t]);
            if (has2h) sh1[t * NH2 + j2] = tanh_fast(s2[t]);
        }
    }
    __syncwarp();

    {
        const float w2a = sW2[j1];
        const float w2b = has2h ? sW2[j2] : 0.0f;
        #pragma unroll
        for (int t = 0; t < APW; t++) {
            float v = sh1[t * NH2 + j1] * w2a;
            if (has2h) v += sh1[t * NH2 + j2] * w2b;
            #pragma unroll
            for (int o = 16; o > 0; o >>= 1) v += __shfl_down_sync(0xffffffffu, v, o);
            if (lane == 0) {
                const float e = v + b2v;
                Ei[abase + t] = e;
                atomicAdd(&Etot[(abase + t) >> 8], e);
            }
        }
    }
    __syncwarp();

    {
        const float w2a = sW2[j1];
        const float w2b = has2h ? sW2[j2] : 0.0f;
        #pragma unroll
        for (int t = 0; t < APW; t++) {
            const float h1v = sh1[t * NH2 + j1];
            sh1[t * NH2 + j1] = w2a * (1.0f - h1v * h1v);
            if (has2h) {
                const float h2v = sh1[t * NH2 + j2];
                sh1[t * NH2 + j2] = w2b * (1.0f - h2v * h2v);
            }
        }
    }
    __syncwarp();

    {
        float s1[APW], s2[APW];
        #pragma unroll
        for (int t = 0; t < APW; t++) { s1[t] = 0.0f; s2[t] = 0.0f; }
        #pragma unroll
        for (int j = 0; j < NH2; j++) {
            const float w1 = sW1[j1 * NH2 + j];
            const float w2 = has2h ? sW1[j2 * NH2 + j] : 0.0f;
            #pragma unroll
            for (int t = 0; t < APW; t++) {
                const float gv = sh1[t * NH2 + j];
                s1[t] += w1 * gv;
                s2[t] += w2 * gv;
            }
        }
        #pragma unroll
        for (int t = 0; t < APW; t++) {
            const float h1v = sh0[t * NH1 + j1];
            sh0[t * NH1 + j1] = s1[t] * (1.0f - h1v * h1v);
            if (has2h) {
                const float h2v = sh0[t * NH1 + j2];
                sh0[t * NH1 + j2] = s2[t] * (1.0f - h2v * h2v);
            }
        }
    }
    __syncwarp();

    {
        const int f2 = lane + 32;
        const bool has2f = (f2 < NF);
        float s1[APW], s2[APW];
        #pragma unroll
        for (int t = 0; t < APW; t++) { s1[t] = 0.0f; s2[t] = 0.0f; }
        #pragma unroll
        for (int i = 0; i < NH1; i++) {
            const float w1 = sW0[lane * NH1 + i];
            const float w2 = has2f ? sW0[f2 * NH1 + i] : 0.0f;
            #pragma unroll
            for (int t = 0; t < APW; t++) {
                const float gv = sh0[t * NH1 + i];
                s1[t] += w1 * gv;
                s2[t] += w2 * gv;
            }
        }
        #pragma unroll
        for (int t = 0; t < APW; t++) {
            g_dE[(size_t)(abase + t) * NF + lane] = s1[t];
            if (has2f) g_dE[(size_t)(abase + t) * NF + f2] = s2[t];
        }
    }
}

// ---------------------------------------------------------------------------
// Kernel 3: Force — FROZEN R13 body (30 regs = exactly 8 CTAs/SM; every
// prefetch variant — regs x2, cp.async — regressed). Only delta: bn0 offset.
// ---------------------------------------------------------------------------
__global__ void __launch_bounds__(256) force_kernel(
    int bn0,
    const float* __restrict__ dfeat,
    const void* __restrict__ neighbor,
    float* __restrict__ force)
{
    __shared__ __align__(16) float sdE[NN * NF];   // 4200 floats = 16.8 KB
    __shared__ int   snbr[NN];
    __shared__ float sred[3][8];

    const int tid = threadIdx.x;
    const int bn  = bn0 + blockIdx.x;    // b*NATOM + n
    const int b   = bn >> 8;

    if (tid < NN) {
        int j;
        if (g_nbr_is32) j = ((const int*)neighbor)[(size_t)bn * NN + tid];
        else            j = (int)((const long long*)neighbor)[(size_t)bn * NN + tid];
        snbr[tid] = j;
    }
    __syncthreads();

    {
        const float* dEb = g_dE + (size_t)b * NATOM * NF;
        float2* sdE2 = (float2*)sdE;
        for (int i2 = tid; i2 < NN * NF / 2; i2 += 256) {
            const int k  = (2 * i2) / NF;
            const int f  = 2 * i2 - k * NF;
            const int j  = snbr[k];
            float2 v;
            if (j == 0) { v.x = 0.0f; v.y = 0.0f; }
            else        { v = *(const float2*)(dEb + (j - 1) * NF + f); }
            sdE2[i2] = v;
        }
    }
    __syncthreads();

    const float4* __restrict__ df4 =
        (const float4*)(dfeat + (size_t)bn * ROWLEN);
    const float4* __restrict__ sdE4 = (const float4*)sdE;

    float a0 = 0.0f, a1 = 0.0f, a2 = 0.0f;
    for (int g = tid; g < NGRP; g += 256) {
        const float4 w  = sdE4[g];
        const float4 v0 = __ldcs(&df4[3 * g + 0]);
        const float4 v1 = __ldcs(&df4[3 * g + 1]);
        const float4 v2 = __ldcs(&df4[3 * g + 2]);
        a0 += w.x * v0.x;  a1 += w.x * v0.y;  a2 += w.x * v0.z;
        a0 += w.y * v0.w;  a1 += w.y * v1.x;  a2 += w.y * v1.y;
        a0 += w.z * v1.z;  a1 += w.z * v1.w;  a2 += w.z * v2.x;
        a0 += w.w * v2.y;  a1 += w.w * v2.z;  a2 += w.w * v2.w;
    }

    #pragma unroll
    for (int o = 16; o > 0; o >>= 1) {
        a0 += __shfl_down_sync(0xffffffffu, a0, o);
        a1 += __shfl_down_sync(0xffffffffu, a1, o);
        a2 += __shfl_down_sync(0xffffffffu, a2, o);
    }
    const int warp = tid >> 5;
    if ((tid & 31) == 0) { sred[0][warp] = a0; sred[1][warp] = a1; sred[2][warp] = a2; }
    __syncthreads();

    if (tid < 3) {
        float s = 0.0f;
        #pragma unroll
        for (int w = 0; w < 8; w++) s += sred[tid][w];
        force[(size_t)bn * 3 + tid] = s;
    }
}

// ---------------------------------------------------------------------------
// Static-init stream/event resources (no device memory — allocation guards
// track memory only; streams/events are context resources).
// ---------------------------------------------------------------------------
namespace {
struct OverlapRes {
    cudaStream_t s2 = nullptr;
    cudaEvent_t  eFork = nullptr, eJoin = nullptr;
    OverlapRes() {
        cudaStreamCreateWithFlags(&s2, cudaStreamNonBlocking);
        cudaEventCreateWithFlags(&eFork, cudaEventDisableTiming);
        cudaEventCreateWithFlags(&eJoin, cudaEventDisableTiming);
    }
};
OverlapRes g_res;
}

// ---------------------------------------------------------------------------
extern "C" void kernel_launch(void* const* d_in, const int* in_sizes, int n_in,
                              void* d_out, int out_size)
{
    const float* image    = (const float*)d_in[0];
    const float* dfeat    = (const float*)d_in[1];
    const void*  neighbor = d_in[2];
    const float* W0_0 = (const float*)d_in[3];
    const float* b0_0 = (const float*)d_in[4];
    const float* W1_0 = (const float*)d_in[5];
    const float* b1_0 = (const float*)d_in[6];
    const float* W2_0 = (const float*)d_in[7];
    const float* b2_0 = (const float*)d_in[8];
    const float* W0_1 = (const float*)d_in[9];
    const float* b0_1 = (const float*)d_in[10];
    const float* W1_1 = (const float*)d_in[11];
    const float* b1_1 = (const float*)d_in[12];
    const float* W2_1 = (const float*)d_in[13];
    const float* b2_1 = (const float*)d_in[14];

    float* out   = (float*)d_out;
    float* Etot  = out;                       // [32]
    float* Ei    = out + BB;                  // [32*256]
    float* Force = out + BB + BB * NATOM;     // [32*256*3]

    cudaMemsetAsync(Etot, 0, BB * sizeof(float));

    // half A: batches 0..15
    mlp_kernel<<<HALF_ATOMS / 32, 256>>>(
        0, image, (const unsigned int*)neighbor,
        W0_0, b0_0, W1_0, b1_0, W2_0, b2_0,
        W0_1, b0_1, W1_1, b1_1, W2_1, b2_1,
        Ei, Etot);

    // fork: mlp half B runs on s2 concurrently with force half A on stream 0
    cudaEventRecord(g_res.eFork, 0);
    cudaStreamWaitEvent(g_res.s2, g_res.eFork, 0);

    mlp_kernel<<<HALF_ATOMS / 32, 256, 0, g_res.s2>>>(
        HALF_ATOMS, image, (const unsigned int*)neighbor,
        W0_0, b0_0, W1_0, b1_0, W2_0, b2_0,
        W0_1, b0_1, W1_1, b1_1, W2_1, b2_1,
        Ei, Etot);
    cudaEventRecord(g_res.eJoin, g_res.s2);

    force_kernel<<<HALF_BN, 256>>>(0, dfeat, neighbor, Force);

    // join: force half B needs dE of batches 16..31
    cudaStreamWaitEvent(0, g_res.eJoin, 0);
    force_kernel<<<HALF_BN, 256>>>(HALF_BN, dfeat, neighbor, Force);
}